// round 17
// baseline (speedup 1.0000x reference)
#include <cuda_runtime.h>
#include <cuda_fp16.h>
#include <cstdint>
#include <cstddef>

// Problem dims: B=4, T=2048 -> BT=8192 tokens, D=1024, E=8, I=1024
#define BT_ 8192
#define D_  1024
#define E_  8
#define I_  1024

#define GOLDEN_CENTER 0.36787944117144233f
#define GOLDEN_LOWER  0.21231792754821915f
#define GOLDEN_UPPER  0.5f

// ---------------------------------------------------------------------------
// Device scratch (static; no runtime allocation)
// ---------------------------------------------------------------------------
__device__ __half g_xq[BT_ * D_];                      // x fp16 [t][d]
__device__ __half g_gq[E_ * D_ * I_];                  // Wg^T fp16 [e][i][d]
__device__ __half g_uq[E_ * D_ * I_];                  // Wu^T fp16 [e][i][d]
__device__ __half g_dq[E_ * D_ * I_];                  // Wd^T fp16 [e][d][i]
__device__ __half g_gate[(size_t)E_ * BT_ * I_];       // gate fp16 compacted [e][slot][i]
__device__ __half g_hq[(size_t)E_ * BT_ * I_];         // h' compacted fp16 [e][slot][i]
__device__ float  g_w[BT_ * E_];                       // routing weights [t][e]
__device__ int    g_tok[E_ * BT_];                     // compacted token ids per expert
__device__ int    g_cnt[E_];                           // active token count per expert
__device__ __half g_part[(size_t)E_ * BT_ * D_];       // per-expert partial out fp16 [e][t][d]

// ---------------------------------------------------------------------------
// helpers
// ---------------------------------------------------------------------------
__device__ __forceinline__ void hmma16(float c[4], const uint32_t a[4], const uint32_t b[2]) {
    asm volatile(
        "mma.sync.aligned.m16n8k16.row.col.f32.f16.f16.f32 "
        "{%0,%1,%2,%3},{%4,%5,%6,%7},{%8,%9},{%0,%1,%2,%3};\n"
        : "+f"(c[0]), "+f"(c[1]), "+f"(c[2]), "+f"(c[3])
        : "r"(a[0]), "r"(a[1]), "r"(a[2]), "r"(a[3]), "r"(b[0]), "r"(b[1]));
}
__device__ __forceinline__ void ldsm4(uint32_t r[4], uint32_t addr) {
    asm volatile("ldmatrix.sync.aligned.m8n8.x4.shared.b16 {%0,%1,%2,%3}, [%4];"
        : "=r"(r[0]), "=r"(r[1]), "=r"(r[2]), "=r"(r[3]) : "r"(addr));
}
__device__ __forceinline__ void cp16(uint32_t dst, const void* src) {
    asm volatile("cp.async.cg.shared.global [%0], [%1], 16;\n" :: "r"(dst), "l"(src) : "memory");
}
__device__ __forceinline__ void cpcommit() { asm volatile("cp.async.commit_group;\n" ::: "memory"); }
__device__ __forceinline__ void cpwait2()  { asm volatile("cp.async.wait_group 2;\n" ::: "memory"); }
__device__ __forceinline__ float siluf(float v) { return v / (1.0f + expf(-v)); }

// K=32 stage layout: rows 64 data bytes + 16 pad = 80B (proven conflict-free)
#define RB     80u
#define KT     32        // K halfs per stage (64 bytes)
#define NSTG   4u
// gemm_g/gemm_u: CTA 128m x 64n; A 128 rows (10240B) + B 64 rows (5120B)
#define GAT    10240u
#define GST    15360u
// gemm_d: CTA 64m x 128n; A 64 rows (5120B) + B 128 rows (10240B)
#define DAT    5120u
#define DST    15360u

// ---------------------------------------------------------------------------
// Routing + x->fp16, 2 warps per token; compensated fp32 accumulation.
// ---------------------------------------------------------------------------
__global__ __launch_bounds__(256) void routing_kernel(
    const float* __restrict__ x, const float* __restrict__ Wr,
    const float* __restrict__ temp)
{
    __shared__ float s_s[4][2][E_], s_c[4][2][E_];
    int tid = threadIdx.x;
    int warp = tid >> 5, lane = tid & 31;
    int pair = warp >> 1, h = warp & 1;
    int t = blockIdx.x * 4 + pair;

    const float* xr = x + (size_t)t * D_;
    float s[E_], c[E_];
#pragma unroll
    for (int e = 0; e < E_; e++) { s[e] = 0.0f; c[e] = 0.0f; }

#pragma unroll 4
    for (int d0 = lane + 32 * h; d0 < D_; d0 += 64) {
        float xv = __ldg(xr + d0);
        float4 wa = *(const float4*)(Wr + d0 * E_);
        float4 wb = *(const float4*)(Wr + d0 * E_ + 4);
        float wv[E_] = {wa.x, wa.y, wa.z, wa.w, wb.x, wb.y, wb.z, wb.w};
#pragma unroll
        for (int e = 0; e < E_; e++) {
            float p   = xv * wv[e];
            float err = fmaf(xv, wv[e], -p);
            float tt  = s[e] + p;
            float e1  = (fabsf(s[e]) >= fabsf(p)) ? ((s[e] - tt) + p)
                                                  : ((p - tt) + s[e]);
            s[e] = tt;
            c[e] += e1 + err;
        }
    }
#pragma unroll
    for (int off = 16; off > 0; off >>= 1) {
#pragma unroll
        for (int e = 0; e < E_; e++) {
            float s2 = __shfl_down_sync(0xffffffffu, s[e], off);
            float c2 = __shfl_down_sync(0xffffffffu, c[e], off);
            float tt = s[e] + s2;
            float e1 = (fabsf(s[e]) >= fabsf(s2)) ? ((s[e] - tt) + s2)
                                                  : ((s2 - tt) + s[e]);
            s[e] = tt;
            c[e] += c2 + e1;
        }
    }
    if (lane == 0) {
#pragma unroll
        for (int e = 0; e < E_; e++) { s_s[pair][h][e] = s[e]; s_c[pair][h][e] = c[e]; }
    }

    __half* xo = g_xq + (size_t)t * D_;
#pragma unroll
    for (int j = 0; j < 4; j++) {
        int d = (lane + 32 * h + 64 * j) * 4;
        float4 v = *(const float4*)(xr + d);
        *(__half2*)(xo + d)     = __floats2half2_rn(v.x, v.y);
        *(__half2*)(xo + d + 2) = __floats2half2_rn(v.z, v.w);
    }
    __syncthreads();

    if (h == 0 && lane == 0) {
        float T = temp[0];
        float dist[E_], wv[E_];
        float wsum = 0.0f;
#pragma unroll
        for (int e = 0; e < E_; e++) {
            float s0 = s_s[pair][0][e], s1 = s_s[pair][1][e];
            float tt = s0 + s1;
            float e1 = (fabsf(s0) >= fabsf(s1)) ? ((s0 - tt) + s1)
                                                : ((s1 - tt) + s0);
            float z = (tt + (s_c[pair][0][e] + s_c[pair][1][e] + e1)) / T;
            float inh = 1.0f / (1.0f + expf(-z));
            dist[e] = fabsf(inh - GOLDEN_CENTER);
            bool zone = (inh >= GOLDEN_LOWER) && (inh <= GOLDEN_UPPER);
            wv[e] = zone ? expf(-dist[e] / 0.1f) : 0.0f;
            wsum += wv[e];
        }
        if (wsum < 1e-8f) {
            float fb[E_];
#pragma unroll
            for (int e = 0; e < E_; e++) fb[e] = expf(-dist[e] / 0.3f);
            int i1 = 0;
#pragma unroll
            for (int e = 1; e < E_; e++) if (fb[e] > fb[i1]) i1 = e;
            int i2 = (i1 == 0) ? 1 : 0;
#pragma unroll
            for (int e = 0; e < E_; e++)
                if (e != i1 && fb[e] > fb[i2]) i2 = e;
            float sc = fmaxf(fb[i1] + fb[i2], 1e-8f);
#pragma unroll
            for (int e = 0; e < E_; e++)
                wv[e] = (e == i1 || e == i2) ? fb[e] / sc : 0.0f;
        }
        float s2 = 0.0f;
#pragma unroll
        for (int e = 0; e < E_; e++) s2 += wv[e];
        float inv = 1.0f / fmaxf(s2, 1e-8f);
#pragma unroll
        for (int e = 0; e < E_; e++) g_w[t * E_ + e] = wv[e] * inv;
    }
}

// ---------------------------------------------------------------------------
// Deterministic per-expert compaction (ordered by token id; no atomics).
// ---------------------------------------------------------------------------
__global__ __launch_bounds__(256) void compact_kernel()
{
    __shared__ int wsum[8];
    __shared__ int sbase;
    int e = blockIdx.x, tid = threadIdx.x, lane = tid & 31, wid = tid >> 5;
    if (tid == 0) sbase = 0;
    __syncthreads();

#pragma unroll 1
    for (int cch = 0; cch < BT_ / 256; cch++) {
        int t = cch * 256 + tid;
        int a = (g_w[t * E_ + e] != 0.0f) ? 1 : 0;
        unsigned m = __ballot_sync(0xffffffffu, a);
        int pos = __popc(m & ((1u << lane) - 1u));
        if (lane == 0) wsum[wid] = __popc(m);
        __syncthreads();
        int wbase = 0;
#pragma unroll
        for (int k = 0; k < 8; k++) if (k < wid) wbase += wsum[k];
        int tot = 0;
#pragma unroll
        for (int k = 0; k < 8; k++) tot += wsum[k];
        int base = sbase;
        __syncthreads();
        if (a) g_tok[e * BT_ + base + wbase + pos] = t;
        if (tid == 0) sbase = base + tot;
        __syncthreads();
    }

    int cnt = sbase;
    int pad = (cnt + 127) & ~127;
    for (int sidx = cnt + tid; sidx < pad; sidx += 256) g_tok[e * BT_ + sidx] = 0;
    if (tid == 0) g_cnt[e] = cnt;
}

// ---------------------------------------------------------------------------
// transpose + fp16, all 3 weight tensors in one launch (z = 24)
// ---------------------------------------------------------------------------
__global__ void convT_kernel(
    const float* __restrict__ in0, const float* __restrict__ in1,
    const float* __restrict__ in2,
    __half* __restrict__ o0, __half* __restrict__ o1, __half* __restrict__ o2)
{
    __shared__ float t[32][33];
    int zz = blockIdx.z;
    int which = zz >> 3, e = zz & 7;
    const float* in = (which == 0) ? in0 : (which == 1) ? in1 : in2;
    __half* oq      = (which == 0) ? o0  : (which == 1) ? o1  : o2;

    const float* ip = in + ((size_t)e << 20);
    __half* op = oq + ((size_t)e << 20);
    int r0 = blockIdx.y * 32, c0 = blockIdx.x * 32;
    int tx = threadIdx.x, ty = threadIdx.y;

#pragma unroll
    for (int j = ty; j < 32; j += 8)
        t[j][tx] = ip[(size_t)(r0 + j) * 1024 + c0 + tx];
    __syncthreads();

    int rh = (tx & 15) * 2;
    int jh = tx >> 4;
#pragma unroll
    for (int k = ty; k < 16; k += 8) {
        int j = k * 2 + jh;
        __half2 v = __floats2half2_rn(t[rh][j], t[rh + 1][j]);
        *(__half2*)(op + (size_t)(c0 + j) * 1024 + r0 + rh) = v;
    }
}

// ---------------------------------------------------------------------------
// GEMM g/u shared body: CTA 128slots x 64n, 8 warps (4m x 2n), warp 32x32.
// KT=32, 4-stage ring (wait_group 2), smem 60KB -> 3 CTAs/SM.
// MODE 0: write gate fp16.  MODE 1: read gate, write h' = w*silu(g)*u.
// ---------------------------------------------------------------------------
template<int MODE>
__device__ __forceinline__ void gemm_gu_body()
{
    const int e  = blockIdx.z;
    const int m0 = blockIdx.y * 128;
    const int cnt = __ldg(&g_cnt[e]);
    if (m0 >= cnt) return;

    extern __shared__ char smem[];
    const uint32_t sb = (uint32_t)__cvta_generic_to_shared(smem);
    const int n0 = blockIdx.x * 64;

    const __half* Bp = (MODE == 0 ? g_gq : g_uq) + ((size_t)e * I_ + n0) * D_;

    const int tid = threadIdx.x, lane = tid & 31, warp = tid >> 5;
    const int wm = warp & 3, wn = warp >> 2;
    const int g = lane >> 2, tg = lane & 3;
    const int lr = tid >> 2, lc8 = (tid & 3) * 8;
    const uint32_t adst1 = (uint32_t)lr * RB + (uint32_t)(tid & 3) * 16;
    const uint32_t adst2 = (uint32_t)(lr + 64) * RB + (uint32_t)(tid & 3) * 16;

    const __half* arow0 = g_xq + (size_t)__ldg(&g_tok[e * BT_ + m0 + lr]) * D_;
    const __half* arow1 = g_xq + (size_t)__ldg(&g_tok[e * BT_ + m0 + lr + 64]) * D_;

    const uint32_t aoffL = (uint32_t)((lane & 7) + ((lane >> 3) & 1) * 8) * RB + (lane >> 4) * 16;
    const uint32_t boffL = (uint32_t)((lane & 7) + ((lane >> 4) & 1) * 8) * RB + ((lane >> 3) & 1) * 16;
    const uint32_t aro = (uint32_t)(wm * 32) * RB;
    const uint32_t bro = GAT + (uint32_t)(wn * 32) * RB;

    float acc[2][4][4];
#pragma unroll
    for (int mt = 0; mt < 2; mt++)
#pragma unroll
        for (int nt = 0; nt < 4; nt++)
#pragma unroll
            for (int i = 0; i < 4; i++) acc[mt][nt][i] = 0.0f;

#define ISSUE_G(buf, k0) do {                                          \
        uint32_t st_ = sb + (uint32_t)(buf) * GST;                     \
        cp16(st_ + adst1, arow0 + (k0) + lc8);                         \
        cp16(st_ + adst2, arow1 + (k0) + lc8);                         \
        cp16(st_ + GAT + adst1, Bp + (size_t)lr * D_ + (k0) + lc8);    \
        cpcommit();                                                    \
    } while (0)

    const int NS = D_ / KT;   // 32
    ISSUE_G(0, 0); ISSUE_G(1, KT); ISSUE_G(2, 2 * KT);

#pragma unroll 1
    for (int st = 0; st < NS; st++) {
        cpwait2();
        __syncthreads();
        if (st + 3 < NS) ISSUE_G((st + 3) & 3, (st + 3) * KT);
        else cpcommit();

        const uint32_t stb = sb + (uint32_t)(st & 3) * GST;
#pragma unroll
        for (int ks = 0; ks < 2; ks++) {
            const uint32_t kb = (uint32_t)ks * 32u;
            uint32_t af[2][4];
#pragma unroll
            for (int mt = 0; mt < 2; mt++)
                ldsm4(af[mt], stb + aro + (uint32_t)(mt * 16) * RB + aoffL + kb);
            uint32_t bf[2][4];
#pragma unroll
            for (int p = 0; p < 2; p++)
                ldsm4(bf[p], stb + bro + (uint32_t)(p * 16) * RB + boffL + kb);
#pragma unroll
            for (int mt = 0; mt < 2; mt++)
#pragma unroll
                for (int p = 0; p < 2; p++)
#pragma unroll
                    for (int q = 0; q < 2; q++)
                        hmma16(acc[mt][2 * p + q], af[mt], &bf[p][2 * q]);
        }
    }
#undef ISSUE_G

    if (MODE == 0) {
        __half* G = g_gate + (size_t)e * BT_ * I_;
#pragma unroll
        for (int mt = 0; mt < 2; mt++) {
            int r0 = m0 + wm * 32 + mt * 16 + g;
#pragma unroll
            for (int nt = 0; nt < 4; nt++) {
                int c0 = n0 + wn * 32 + nt * 8 + tg * 2;
                *(__half2*)(G + (size_t)r0 * I_ + c0)       = __floats2half2_rn(acc[mt][nt][0], acc[mt][nt][1]);
                *(__half2*)(G + (size_t)(r0 + 8) * I_ + c0) = __floats2half2_rn(acc[mt][nt][2], acc[mt][nt][3]);
            }
        }
    } else {
        const __half* G = g_gate + (size_t)e * BT_ * I_;
        __half* H = g_hq + (size_t)e * BT_ * I_;
#pragma unroll
        for (int mt = 0; mt < 2; mt++) {
            int r0 = m0 + wm * 32 + mt * 16 + g;
            float w0 = g_w[__ldg(&g_tok[e * BT_ + r0]) * E_ + e];
            float w1 = g_w[__ldg(&g_tok[e * BT_ + r0 + 8]) * E_ + e];
#pragma unroll
            for (int nt = 0; nt < 4; nt++) {
                int c0 = n0 + wn * 32 + nt * 8 + tg * 2;
                float2 g0 = __half22float2(*(const __half2*)(G + (size_t)r0 * I_ + c0));
                float2 g1 = __half22float2(*(const __half2*)(G + (size_t)(r0 + 8) * I_ + c0));
                float h0 = w0 * siluf(g0.x) * acc[mt][nt][0];
                float h1 = w0 * siluf(g0.y) * acc[mt][nt][1];
                float h2 = w1 * siluf(g1.x) * acc[mt][nt][2];
                float h3 = w1 * siluf(g1.y) * acc[mt][nt][3];
                *(__half2*)(H + (size_t)r0 * I_ + c0)       = __floats2half2_rn(h0, h1);
                *(__half2*)(H + (size_t)(r0 + 8) * I_ + c0) = __floats2half2_rn(h2, h3);
            }
        }
    }
}

__global__ __launch_bounds__(256, 3) void gemm_g_kernel() { gemm_gu_body<0>(); }
__global__ __launch_bounds__(256, 3) void gemm_u_kernel() { gemm_gu_body<1>(); }

// ---------------------------------------------------------------------------
// gemm_d: CTA 64slots x 128n, 8 warps (2m x 4n), warp 32x32. KT=32,
// 4-stage ring, smem 60KB -> 3 CTAs/SM. fp16 scatter to g_part.
// ---------------------------------------------------------------------------
__global__ __launch_bounds__(256, 3) void gemm_d_kernel()
{
    const int e  = blockIdx.z;
    const int m0 = blockIdx.y * 64;
    const int cnt = __ldg(&g_cnt[e]);
    if (m0 >= cnt) return;

    extern __shared__ char smem[];
    const uint32_t sb = (uint32_t)__cvta_generic_to_shared(smem);
    const int n0 = blockIdx.x * 128;

    const __half* Ap = g_hq + ((size_t)e * BT_ + m0) * I_;
    const __half* Bp = g_dq + ((size_t)e * D_ + n0) * I_;

    const int tid = threadIdx.x, lane = tid & 31, warp = tid >> 5;
    const int wm = warp & 1, wn = warp >> 1;
    const int g = lane >> 2, tg = lane & 3;
    const int lr = tid >> 2, lc8 = (tid & 3) * 8;
    const uint32_t ad = (uint32_t)lr * RB + (uint32_t)(tid & 3) * 16;
    const uint32_t bd2 = (uint32_t)(lr + 64) * RB + (uint32_t)(tid & 3) * 16;

    const uint32_t aoffL = (uint32_t)((lane & 7) + ((lane >> 3) & 1) * 8) * RB + (lane >> 4) * 16;
    const uint32_t boffL = (uint32_t)((lane & 7) + ((lane >> 4) & 1) * 8) * RB + ((lane >> 3) & 1) * 16;
    const uint32_t aro = (uint32_t)(wm * 32) * RB;
    const uint32_t bro = DAT + (uint32_t)(wn * 32) * RB;

    float acc[2][4][4];
#pragma unroll
    for (int mt = 0; mt < 2; mt++)
#pragma unroll
        for (int nt = 0; nt < 4; nt++)
#pragma unroll
            for (int i = 0; i < 4; i++) acc[mt][nt][i] = 0.0f;

#define ISSUE_D(buf, k0) do {                                              \
        uint32_t st_ = sb + (uint32_t)(buf) * DST;                         \
        if (lr < 64) cp16(st_ + ad, Ap + (size_t)lr * I_ + (k0) + lc8);    \
        cp16(st_ + DAT + ad,  Bp + (size_t)lr * I_ + (k0) + lc8);          \
        cp16(st_ + DAT + bd2, Bp + (size_t)(lr + 64) * I_ + (k0) + lc8);   \
        cpcommit();                                                        \
    } while (0)

    const int NS = I_ / KT;   // 32
    ISSUE_D(0, 0); ISSUE_D(1, KT); ISSUE_D(2, 2 * KT);

#pragma unroll 1
    for (int st = 0; st < NS; st++) {
        cpwait2();
        __syncthreads();
        if (st + 3 < NS) ISSUE_D((st + 3) & 3, (st + 3) * KT);
        else cpcommit();

        const uint32_t stb = sb + (uint32_t)(st & 3) * DST;
#pragma unroll
        for (int ks = 0; ks < 2; ks++) {
            const uint32_t kb = (uint32_t)ks * 32u;
            uint32_t af[2][4];
#pragma unroll
            for (int mt = 0; mt < 2; mt++)
                ldsm4(af[mt], stb + aro + (uint32_t)(mt * 16) * RB + aoffL + kb);
            uint32_t bf[2][4];
#pragma unroll
            for (int p = 0; p < 2; p++)
                ldsm4(bf[p], stb + bro + (uint32_t)(p * 16) * RB + boffL + kb);
#pragma unroll
            for (int mt = 0; mt < 2; mt++)
#pragma unroll
                for (int p = 0; p < 2; p++)
#pragma unroll
                    for (int q = 0; q < 2; q++)
                        hmma16(acc[mt][2 * p + q], af[mt], &bf[p][2 * q]);
        }
    }
#undef ISSUE_D

#pragma unroll
    for (int mt = 0; mt < 2; mt++) {
        int s0 = m0 + wm * 32 + mt * 16 + g;
        int s1 = s0 + 8;
        if (s0 < cnt) {
            int t0 = __ldg(&g_tok[e * BT_ + s0]);
            __half* P = g_part + ((size_t)e * BT_ + t0) * D_;
#pragma unroll
            for (int nt = 0; nt < 4; nt++) {
                int c0 = n0 + wn * 32 + nt * 8 + tg * 2;
                *(__half2*)(P + c0) = __floats2half2_rn(acc[mt][nt][0], acc[mt][nt][1]);
            }
        }
        if (s1 < cnt) {
            int t1 = __ldg(&g_tok[e * BT_ + s1]);
            __half* P = g_part + ((size_t)e * BT_ + t1) * D_;
#pragma unroll
            for (int nt = 0; nt < 4; nt++) {
                int c0 = n0 + wn * 32 + nt * 8 + tg * 2;
                *(__half2*)(P + c0) = __floats2half2_rn(acc[mt][nt][2], acc[mt][nt][3]);
            }
        }
    }
}

// ---------------------------------------------------------------------------
// reduce (flat): out[t][d] = sum_e active part[e][t][d]
// ---------------------------------------------------------------------------
__global__ __launch_bounds__(256) void reduce_kernel(float* __restrict__ out)
{
    int gid = blockIdx.x * 256 + threadIdx.x;
    int t = gid >> 8;
    int d = (gid & 255) * 4;

    const float* wr = g_w + t * E_;
    float4 acc = make_float4(0.0f, 0.0f, 0.0f, 0.0f);
#pragma unroll
    for (int e = 0; e < E_; e++) {
        float w = __ldg(wr + e);
        if (w != 0.0f) {
            const __half2* P = (const __half2*)(g_part + ((size_t)e * BT_ + t) * D_ + d);
            float2 f0 = __half22float2(P[0]), f1 = __half22float2(P[1]);
            acc.x += f0.x; acc.y += f0.y; acc.z += f1.x; acc.w += f1.y;
        }
    }
    *(float4*)(out + (size_t)t * D_ + d) = acc;
}

// ---------------------------------------------------------------------------
// launch
// ---------------------------------------------------------------------------
extern "C" void kernel_launch(void* const* d_in, const int* in_sizes, int n_in,
                              void* d_out, int out_size)
{
    const float* x    = (const float*)d_in[0];
    const float* Wg   = (const float*)d_in[1];
    const float* Wu   = (const float*)d_in[2];
    const float* Wd   = (const float*)d_in[3];
    const float* Wr   = (const float*)d_in[4];
    const float* temp = (const float*)d_in[5];
    float* out = (float*)d_out;

    cudaFuncSetAttribute(gemm_g_kernel, cudaFuncAttributeMaxDynamicSharedMemorySize, NSTG * GST);
    cudaFuncSetAttribute(gemm_u_kernel, cudaFuncAttributeMaxDynamicSharedMemorySize, NSTG * GST);
    cudaFuncSetAttribute(gemm_d_kernel, cudaFuncAttributeMaxDynamicSharedMemorySize, NSTG * DST);

    __half *gq, *uq, *dq;
    cudaGetSymbolAddress((void**)&gq, g_gq);
    cudaGetSymbolAddress((void**)&uq, g_uq);
    cudaGetSymbolAddress((void**)&dq, g_dq);

    routing_kernel<<<BT_ / 4, 256>>>(x, Wr, temp);      // 1 (+ x->fp16)
    compact_kernel<<<E_, 256>>>();                      // 2

    dim3 gt(32, 32, 3 * E_), bt(32, 8);
    convT_kernel<<<gt, bt>>>(Wg, Wu, Wd, gq, uq, dq);   // 3

    dim3 gGU(I_ / 64, BT_ / 128, E_);
    gemm_g_kernel<<<gGU, 256, NSTG * GST>>>();          // 4
    gemm_u_kernel<<<gGU, 256, NSTG * GST>>>();          // 5

    dim3 gD(D_ / 128, BT_ / 64, E_);
    gemm_d_kernel<<<gD, 256, NSTG * DST>>>();           // 6

    reduce_kernel<<<BT_, 256>>>(out);                   // 7
}